// round 9
// baseline (speedup 1.0000x reference)
#include <cuda_runtime.h>
#include <math.h>
#include <stdint.h>

#define BB 16384

__device__ float g_mempre[(size_t)BB * 4096];   // 256 MB
__device__ float g_ww[BB * 64];                 //   4 MB

__device__ __forceinline__ float sigmoidf_(float x) { return 1.0f / (1.0f + __expf(-x)); }

__device__ __forceinline__ uint32_t smem_u32(const void* p) {
    uint32_t a;
    asm("{ .reg .u64 t; cvta.to.shared.u64 t, %1; cvt.u32.u64 %0, t; }" : "=r"(a) : "l"(p));
    return a;
}
__device__ __forceinline__ void ldsm4(uint32_t* d, uint32_t addr) {
    asm volatile("ldmatrix.sync.aligned.m8n8.x4.shared.b16 {%0,%1,%2,%3}, [%4];"
        : "=r"(d[0]), "=r"(d[1]), "=r"(d[2]), "=r"(d[3]) : "r"(addr));
}
__device__ __forceinline__ void mma8(float* c, const uint32_t* a, uint32_t b0, uint32_t b1) {
    asm volatile("mma.sync.aligned.m16n8k8.row.col.f32.tf32.tf32.f32 "
        "{%0,%1,%2,%3}, {%4,%5,%6,%7}, {%8,%9}, {%0,%1,%2,%3};"
        : "+f"(c[0]), "+f"(c[1]), "+f"(c[2]), "+f"(c[3])
        : "r"(a[0]), "r"(a[1]), "r"(a[2]), "r"(a[3]), "r"(b0), "r"(b1));
}
__device__ __forceinline__ void cp16(uint32_t dst, const void* src) {
    asm volatile("cp.async.cg.shared.global [%0], [%1], 16;" :: "r"(dst), "l"(src));
}
__device__ __forceinline__ void cp4(uint32_t dst, const void* src) {
    asm volatile("cp.async.ca.shared.global [%0], [%1], 4;" :: "r"(dst), "l"(src));
}
__device__ __forceinline__ void cp_commit() {
    asm volatile("cp.async.commit_group;" ::: "memory");
}
template <int N>
__device__ __forceinline__ void cp_wait() {
    asm volatile("cp.async.wait_group %0;" :: "n"(N) : "memory");
}
// B-operand x4: one k8 step, two n8 tiles (pair p)
__device__ __forceinline__ uint32_t boff4(int NB, int wn, int NW, int p, int lane) {
    return (uint32_t)(((((lane >> 3) & 1) * NB) + wn * NW + p * 16 +
                      (lane & 7) + ((lane >> 4) << 3)) * 16);
}
// swizzled mv/mempre chunk address (64-row tiles)
__device__ __forceinline__ uint32_t r1a(int kb, int row) {
    return (uint32_t)((kb * 64 + (row ^ (kb & 7))) * 16);
}

// ---- SMEM map (bytes), total 106496; 2 CTAs/SM ----
// [0,32768)        c0 chunks (64r x 128k A-chunk); later e1 @0 (16K), z1/add @16384
// [32768,106496)   region:
//   P1:  3 x 24576 pipeline stages @32768; c0-epi stage 64x132 @32768
//   P3:  R1 2x8192 @32768 | Wm1 16384 @49152 | Wsig 24576 @65536
//   P4a: siga 49152 @32768 | EZ B quarter 16384 @81920
//   P4b: zt chunk 8192 @81920 | Wza half 8192 @90112
//   P5:  ww 16384 @32768
#define SMEM_TOTAL 106496

__global__ void __launch_bounds__(256, 2) fused_k(
    const float* __restrict__ qa,  const float* __restrict__ mv,
    const float* __restrict__ We,  const float* __restrict__ be,
    const float* __restrict__ Wemv, const float* __restrict__ bemv,
    const float* __restrict__ Wza, const float* __restrict__ bza,
    const float* __restrict__ Wamv, const float* __restrict__ bamv,
    const float* __restrict__ Wc0, const float* __restrict__ bc0,
    const float* __restrict__ Wm1, const float* __restrict__ bm1,
    const float* __restrict__ Wz,  const float* __restrict__ bz,
    const float* __restrict__ Wzmv, const float* __restrict__ bzmv,
    float* __restrict__ outp)
{
    extern __shared__ char smem[];
    const int tid  = threadIdx.x;
    const int lane = tid & 31;
    const int wid  = tid >> 5;
    const int wm   = wid & 1;     // 2 M-groups of 32 rows
    const int wn   = wid >> 1;    // 4 N-groups
    const int m0   = blockIdx.x * 64;

    uint32_t sb  = smem_u32(smem);
    uint32_t c0b = sb;

    // A-fragment offsets (64-row chunks): one ldsm4 = 16 rows x one k8
    const uint32_t aoff0 = (uint32_t)((((lane >> 4) * 64) + wm * 32 + (lane & 15)) * 16);
    const uint32_t aoff1 = aoff0 + 16 * 16;     // mt=1: +16 rows
    // gate/EZ B (NB=32): x4 = 2 k8 steps x 1 n8
    const uint32_t boffG = (uint32_t)(((lane >> 3) * 32 + wn * 8 + (lane & 7)) * 16);
    const int frow0 = wm * 32 + (lane >> 2);
    const int fc2   = 2 * (lane & 3);

    // ============ P1: c0 = qa * sigmoid(mv @ Wc0 + bc0), 3-stage pipeline ============
    {
        float cacc[2][4][4];
#pragma unroll
        for (int mt = 0; mt < 2; mt++)
#pragma unroll
            for (int nt = 0; nt < 4; nt++)
#pragma unroll
                for (int j = 0; j < 4; j++) cacc[mt][nt][j] = 0.f;

        auto issue1 = [&](int c) {
            uint32_t ab = sb + 32768 + (c % 3) * 24576, bb2 = ab + 8192;
            int kt = c * 32;
#pragma unroll
            for (int i = 0; i < 2; i++) {              // mv: 64r x 32k
                int v = tid + i * 256;
                int kb = v & 7, r = v >> 3;
                cp16(ab + (kb * 64 + r) * 16, &mv[(size_t)(m0 + r) * 4096 + kt + kb * 4]);
            }
#pragma unroll
            for (int i = 0; i < 16; i++) {             // Wc0: 32k x 128n
                int v = tid + i * 256;
                int kl = v >> 7, n = v & 127;
                cp4(bb2 + ((kl >> 2) * 128 + n) * 16 + (kl & 3) * 4,
                    &Wc0[(size_t)(kt + kl) * 128 + n]);
            }
            cp_commit();
        };
        issue1(0); issue1(1);
#pragma unroll 1
        for (int c = 0; c < 128; c++) {
            if (c == 127) cp_wait<0>(); else cp_wait<1>();
            __syncthreads();
            if (c + 2 < 128) issue1(c + 2);
            uint32_t ab = sb + 32768 + (c % 3) * 24576, bb2 = ab + 8192;
#pragma unroll
            for (int s = 0; s < 4; s++) {
                uint32_t a0[4], a1[4];
                ldsm4(a0, ab + aoff0 + s * 2048);
                ldsm4(a1, ab + aoff1 + s * 2048);
#pragma unroll
                for (int p = 0; p < 2; p++) {
                    uint32_t b[4];
                    ldsm4(b, bb2 + boff4(128, wn, 32, p, lane) + s * 4096);
                    mma8(cacc[0][2 * p],     a0, b[0], b[1]);
                    mma8(cacc[0][2 * p + 1], a0, b[2], b[3]);
                    mma8(cacc[1][2 * p],     a1, b[0], b[1]);
                    mma8(cacc[1][2 * p + 1], a1, b[2], b[3]);
                }
            }
        }
        __syncthreads();
        float* stg = (float*)(smem + 32768);
#pragma unroll
        for (int mt = 0; mt < 2; mt++)
#pragma unroll
            for (int nt = 0; nt < 4; nt++) {
                int row = frow0 + mt * 16;
                int col = wn * 32 + nt * 8 + fc2;
                *(float2*)&stg[row * 132 + col]       = make_float2(cacc[mt][nt][0], cacc[mt][nt][1]);
                *(float2*)&stg[(row + 8) * 132 + col] = make_float2(cacc[mt][nt][2], cacc[mt][nt][3]);
            }
        __syncthreads();
#pragma unroll
        for (int i = 0; i < 32; i++) {
            int v = tid + i * 256;
            int row = v >> 7, k = v & 127;
            float c0v = __ldg(&qa[(size_t)(m0 + row) * 128 + k]) *
                        sigmoidf_(stg[row * 132 + k] + __ldg(&bc0[k]));
            *(float*)(smem + ((k >> 2) * 64 + row) * 16 + (k & 3) * 4) = c0v;
        }
        __syncthreads();
    }

    // ============ P3: per 32-col block: gate -> mempre(inplace+STG) -> SIG accumulate ============
    float sacc[2][6][4];
#pragma unroll
    for (int mt = 0; mt < 2; mt++)
#pragma unroll
        for (int nt = 0; nt < 6; nt++)
#pragma unroll
            for (int j = 0; j < 4; j++) sacc[mt][nt][j] = 0.f;
    {
        auto issue_mw = [&](int o) {
            uint32_t r1b_ = sb + 32768 + (o & 1) * 8192;
            int kt = o * 32;
#pragma unroll
            for (int i = 0; i < 2; i++) {              // mv: 64r x 32k, swizzled
                int v = tid + i * 256;
                int kb = v & 7, r = v >> 3;
                cp16(r1b_ + r1a(kb, r), &mv[(size_t)(m0 + r) * 4096 + kt + kb * 4]);
            }
#pragma unroll
            for (int i = 0; i < 16; i++) {             // Wm1 slice: 128k x 32n
                int v = tid + i * 256;
                int kl = v >> 5, n = v & 31;
                cp4(sb + 49152 + ((kl >> 2) * 32 + n) * 16 + (kl & 3) * 4,
                    &Wm1[(size_t)kl * 4096 + kt + n]);
            }
            cp_commit();
        };
        auto issue_sig = [&](int o) {
            int kt = o * 32;
#pragma unroll
            for (int i = 0; i < 24; i++) {             // Wsig: 32k x 192n
                int v = tid + i * 256;
                int kl = v / 192, n = v - kl * 192;
                const float* W = (n < 64) ? Wemv : (n < 128) ? Wzmv : Wamv;
                cp4(sb + 65536 + ((kl >> 2) * 192 + n) * 16 + (kl & 3) * 4,
                    &W[(size_t)(kt + kl) * 64 + (n & 63)]);
            }
            cp_commit();
        };

        issue_mw(0);
#pragma unroll 1
        for (int o = 0; o < 128; o++) {
            cp_wait<0>();
            __syncthreads();                           // mv/Wm1(o) visible; SIG(o-1) done
            issue_sig(o);

            // gate mma: A = c0 (K=128), B = Wm1 (NB=32); 8 steps of 2 k8
            float gacc[2][4];
#pragma unroll
            for (int mt = 0; mt < 2; mt++)
#pragma unroll
                for (int j = 0; j < 4; j++) gacc[mt][j] = 0.f;
#pragma unroll
            for (int s = 0; s < 8; s++) {
                uint32_t ae0[4], ae1[4], ao0[4], ao1[4], b[4];
                ldsm4(ae0, c0b + aoff0 + (2 * s) * 2048);
                ldsm4(ae1, c0b + aoff1 + (2 * s) * 2048);
                ldsm4(ao0, c0b + aoff0 + (2 * s + 1) * 2048);
                ldsm4(ao1, c0b + aoff1 + (2 * s + 1) * 2048);
                ldsm4(b, sb + 49152 + boffG + s * 2048);
                mma8(gacc[0], ae0, b[0], b[1]);
                mma8(gacc[1], ae1, b[0], b[1]);
                mma8(gacc[0], ao0, b[2], b[3]);
                mma8(gacc[1], ao1, b[2], b[3]);
            }
            // mempre = mv * sigmoid(gate + bm1), in place + STG
            const int kt = o * 32;
            const uint32_t r1o = 32768 + (o & 1) * 8192;
            {
                int colb = wn * 8 + fc2;
                float b0v = __ldg(&bm1[kt + colb]);
                float b1v = __ldg(&bm1[kt + colb + 1]);
                int kb = colb >> 2, w0 = colb & 3;
#pragma unroll
                for (int mt = 0; mt < 2; mt++)
#pragma unroll
                    for (int half = 0; half < 2; half++) {
                        int row = frow0 + mt * 16 + half * 8;
                        uint32_t off = r1o + r1a(kb, row) + w0 * 4;
                        float p0 = *(float*)(smem + off) *
                                   sigmoidf_(gacc[mt][half * 2 + 0] + b0v);
                        float p1 = *(float*)(smem + off + 4) *
                                   sigmoidf_(gacc[mt][half * 2 + 1] + b1v);
                        *(float*)(smem + off)     = p0;
                        *(float*)(smem + off + 4) = p1;
                        *(float2*)&g_mempre[(size_t)(m0 + row) * 4096 + kt + colb] =
                            make_float2(p0, p1);
                    }
            }
            __syncthreads();                           // mempre visible; Wm1 free
            if (o < 127) { issue_mw(o + 1); cp_wait<1>(); }
            else         { cp_wait<0>(); }
            __syncthreads();                           // Wsig visible

            // SIG mma: A = mempre (K=32, swizzled), B = Wsig (NB=192)
            uint32_t r1b_ = sb + r1o;
            const int rowb = wm * 32 + (lane & 15);
#pragma unroll
            for (int s = 0; s < 4; s++) {
                int kb0 = 2 * s + (lane >> 4);
                uint32_t a0[4], a1[4];
                ldsm4(a0, r1b_ + (uint32_t)((kb0 * 64 + (rowb ^ (kb0 & 7))) * 16));
                ldsm4(a1, r1b_ + (uint32_t)((kb0 * 64 + ((rowb + 16) ^ (kb0 & 7))) * 16));
#pragma unroll
                for (int p = 0; p < 3; p++) {
                    uint32_t b[4];
                    ldsm4(b, sb + 65536 + boff4(192, wn, 48, p, lane) + s * 6144);
                    mma8(sacc[0][2 * p],     a0, b[0], b[1]);
                    mma8(sacc[0][2 * p + 1], a0, b[2], b[3]);
                    mma8(sacc[1][2 * p],     a1, b[0], b[1]);
                    mma8(sacc[1][2 * p + 1], a1, b[2], b[3]);
                }
            }
        }
    }

    // ============ P4a: sacc dump -> siga; EZ = c0 @ [We|Wz] in 4 quarter passes ============
    __syncthreads();
    {
        float* siga = (float*)(smem + 32768);
#pragma unroll
        for (int mt = 0; mt < 2; mt++)
#pragma unroll
            for (int nt = 0; nt < 6; nt++)
#pragma unroll
                for (int idx = 0; idx < 4; idx++) {
                    int row = frow0 + mt * 16 + (idx >> 1) * 8;
                    int col = wn * 48 + nt * 8 + fc2 + (idx & 1);
                    float bv = (col < 64) ? __ldg(&bemv[col])
                             : (col < 128) ? __ldg(&bzmv[col - 64])
                                           : __ldg(&bamv[col - 128]);
                    siga[row * 192 + col] = sacc[mt][nt][idx] + bv;
                }

        auto issue_ez = [&](int q) {                   // 128k x 32n quarter
#pragma unroll
            for (int i = 0; i < 16; i++) {
                int v = tid + i * 256;
                int kl = v >> 5, n = v & 31;
                int g = q * 32 + n;
                const float* W = (g < 64) ? We : Wz;
                cp4(sb + 81920 + ((kl >> 2) * 32 + n) * 16 + (kl & 3) * 4,
                    &W[(size_t)kl * 64 + (g & 63)]);
            }
            cp_commit();
        };

        float ezacc[4][2][4];
#pragma unroll
        for (int q = 0; q < 4; q++)
#pragma unroll
            for (int mt = 0; mt < 2; mt++)
#pragma unroll
                for (int j = 0; j < 4; j++) ezacc[q][mt][j] = 0.f;

        issue_ez(0);
#pragma unroll 1
        for (int q = 0; q < 4; q++) {
            cp_wait<0>();
            __syncthreads();
#pragma unroll
            for (int s = 0; s < 8; s++) {
                uint32_t ae0[4], ae1[4], ao0[4], ao1[4], b[4];
                ldsm4(ae0, c0b + aoff0 + (2 * s) * 2048);
                ldsm4(ae1, c0b + aoff1 + (2 * s) * 2048);
                ldsm4(ao0, c0b + aoff0 + (2 * s + 1) * 2048);
                ldsm4(ao1, c0b + aoff1 + (2 * s + 1) * 2048);
                ldsm4(b, sb + 81920 + boffG + s * 2048);
                mma8(ezacc[q][0], ae0, b[0], b[1]);
                mma8(ezacc[q][1], ae1, b[0], b[1]);
                mma8(ezacc[q][0], ao0, b[2], b[3]);
                mma8(ezacc[q][1], ao1, b[2], b[3]);
            }
            __syncthreads();
            if (q < 3) issue_ez(q + 1);
        }

        // dump -> e1 @0, z1 @16384 (overwrites c0; all EZ reads done)
        float* e1a = (float*)smem;
        float* z1a = (float*)(smem + 16384);
#pragma unroll
        for (int q = 0; q < 4; q++)
#pragma unroll
            for (int mt = 0; mt < 2; mt++)
#pragma unroll
                for (int idx = 0; idx < 4; idx++) {
                    int row = frow0 + mt * 16 + (idx >> 1) * 8;
                    int col = q * 32 + wn * 8 + fc2 + (idx & 1);
                    float v = ezacc[q][mt][idx];
                    if (col < 64) e1a[row * 64 + col] = sigmoidf_(v + __ldg(&be[col]));
                    else          z1a[row * 64 + (col - 64)] = v + __ldg(&bz[col - 64]);
                }
        __syncthreads();
    }

    // ============ P4b: zt, erase, add ============
    {
        float* e1a  = (float*)smem;
        float* z1a  = (float*)(smem + 16384);
        float* siga = (float*)(smem + 32768);

        float zaacc[2][2][4];
#pragma unroll
        for (int mt = 0; mt < 2; mt++)
#pragma unroll
            for (int nt = 0; nt < 2; nt++)
#pragma unroll
                for (int j = 0; j < 4; j++) zaacc[mt][nt][j] = 0.f;

#pragma unroll 1
        for (int h = 0; h < 2; h++) {
#pragma unroll
            for (int i = 0; i < 8; i++) {              // Wza half: 32k x 64n
                int v = tid + i * 256;
                int kl = v >> 6, n = v & 63;
                cp4(sb + 90112 + ((kl >> 2) * 64 + n) * 16 + (kl & 3) * 4,
                    &Wza[(size_t)(h * 32 + kl) * 64 + n]);
            }
            cp_commit();
            // zt half -> chunk @81920; erase half in place
#pragma unroll
            for (int i = 0; i < 8; i++) {
                int v = tid + i * 256;
                int row = v >> 5, jl = v & 31;
                int j = h * 32 + jl;
                float ztv = sigmoidf_(z1a[row * 64 + j] + siga[row * 192 + 64 + j]);
                *(float*)(smem + 81920 + ((jl >> 2) * 64 + row) * 16 + (jl & 3) * 4) = ztv;
                e1a[row * 64 + j] = sigmoidf_(e1a[row * 64 + j] + sigmoidf_(siga[row * 192 + j]));
            }
            cp_wait<0>();
            __syncthreads();
#pragma unroll
            for (int s = 0; s < 4; s++) {
                uint32_t a0[4], a1[4], b[4];
                ldsm4(a0, sb + 81920 + aoff0 + s * 2048);
                ldsm4(a1, sb + 81920 + aoff1 + s * 2048);
                ldsm4(b, sb + 90112 + boff4(64, wn, 16, 0, lane) + s * 2048);
                mma8(zaacc[0][0], a0, b[0], b[1]);
                mma8(zaacc[0][1], a0, b[2], b[3]);
                mma8(zaacc[1][0], a1, b[0], b[1]);
                mma8(zaacc[1][1], a1, b[2], b[3]);
            }
            __syncthreads();
        }
        // add -> z1 area
#pragma unroll
        for (int mt = 0; mt < 2; mt++)
#pragma unroll
            for (int nt = 0; nt < 2; nt++)
#pragma unroll
                for (int idx = 0; idx < 4; idx++) {
                    int row = frow0 + mt * 16 + (idx >> 1) * 8;
                    int col = wn * 16 + nt * 8 + fc2 + (idx & 1);
                    z1a[row * 64 + col] =
                        tanhf(tanhf(zaacc[mt][nt][idx] + __ldg(&bza[col])) +
                              tanhf(siga[row * 192 + 128 + col]));
                }
        __syncthreads();
        // ww -> @32768 (siga dead)
#pragma unroll
        for (int i = 0; i < 4; i++) {
            int v = tid + i * 256;
            *(float4*)(smem + 32768 + v * 16) = *(const float4*)&g_ww[(size_t)m0 * 64 + v * 4];
        }
        __syncthreads();
    }

    // ============ P5: out = mempre*(1 - w*erase) + w*add ============
    {
        const float* er = (const float*)smem;
        const float* ad = (const float*)(smem + 16384);
        const float* sw = (const float*)(smem + 32768);
#pragma unroll 4
        for (int it = 0; it < 256; it++) {
            int v = tid + it * 256;
            int row = v >> 10, q = v & 1023;
            float4 mp = *(const float4*)&g_mempre[(size_t)(m0 + row) * 4096 + q * 4];
            float w = sw[row * 64 + (q >> 4)];
            float4 e4 = *(const float4*)&er[row * 64 + (q & 15) * 4];
            float4 a4 = *(const float4*)&ad[row * 64 + (q & 15) * 4];
            float4 r;
            r.x = mp.x * (1.f - w * e4.x) + w * a4.x;
            r.y = mp.y * (1.f - w * e4.y) + w * a4.y;
            r.z = mp.z * (1.f - w * e4.z) + w * a4.z;
            r.w = mp.w * (1.f - w * e4.w) + w * a4.w;
            *(float4*)&outp[(size_t)(m0 + row) * 4096 + q * 4] = r;
        }
    }
}

// ---------------- write_weight: softmax(control_key @ memory_key^T) ----------------
__global__ void __launch_bounds__(256) ww_k(const float* __restrict__ ck,
                                            const float* __restrict__ mk)
{
    int g = threadIdx.x >> 6;
    int t = threadIdx.x & 63;
    int b = blockIdx.x * 4 + g;
    __shared__ float sck[4][64];
    __shared__ float pmax[4][2];
    __shared__ float psum[4][2];

    sck[g][t] = ck[b * 64 + t];
    __syncthreads();
    float dot = 0.f;
#pragma unroll 8
    for (int k = 0; k < 64; k++) dot = fmaf(sck[g][k], mk[t * 64 + k], dot);

    float mx = dot;
#pragma unroll
    for (int o = 16; o > 0; o >>= 1) mx = fmaxf(mx, __shfl_xor_sync(0xffffffffu, mx, o));
    int wl = t >> 5;
    if ((t & 31) == 0) pmax[g][wl] = mx;
    __syncthreads();
    mx = fmaxf(pmax[g][0], pmax[g][1]);

    float e = __expf(dot - mx);
    float s = e;
#pragma unroll
    for (int o = 16; o > 0; o >>= 1) s += __shfl_xor_sync(0xffffffffu, s, o);
    if ((t & 31) == 0) psum[g][wl] = s;
    __syncthreads();
    s = psum[g][0] + psum[g][1];

    g_ww[b * 64 + t] = e / s;
}

// ====================== launch ======================
extern "C" void kernel_launch(void* const* d_in, const int* in_sizes, int n_in,
                              void* d_out, int out_size)
{
    const float* control_key  = (const float*)d_in[0];
    const float* control_qa   = (const float*)d_in[1];
    const float* memory_key   = (const float*)d_in[2];
    const float* memory_value = (const float*)d_in[3];
    const float* We   = (const float*)d_in[4];
    const float* be   = (const float*)d_in[5];
    const float* Wemv = (const float*)d_in[6];
    const float* bemv = (const float*)d_in[7];
    const float* Wza  = (const float*)d_in[8];
    const float* bza  = (const float*)d_in[9];
    const float* Wamv = (const float*)d_in[10];
    const float* bamv = (const float*)d_in[11];
    const float* Wc0  = (const float*)d_in[12];
    const float* bc0  = (const float*)d_in[13];
    const float* Wm1  = (const float*)d_in[14];
    const float* bm1  = (const float*)d_in[15];
    const float* Wz   = (const float*)d_in[16];
    const float* bz   = (const float*)d_in[17];
    const float* Wzmv = (const float*)d_in[18];
    const float* bzmv = (const float*)d_in[19];
    float* out = (float*)d_out;

    cudaFuncSetAttribute(fused_k, cudaFuncAttributeMaxDynamicSharedMemorySize, SMEM_TOTAL);

    ww_k<<<BB / 4, 256>>>(control_key, memory_key);

    fused_k<<<BB / 64, 256, SMEM_TOTAL>>>(
        control_qa, memory_value,
        We, be, Wemv, bemv, Wza, bza, Wamv, bamv,
        Wc0, bc0, Wm1, bm1, Wz, bz, Wzmv, bzmv,
        out);
}

// round 10
// speedup vs baseline: 1.0219x; 1.0219x over previous
#include <cuda_runtime.h>
#include <math.h>
#include <stdint.h>

#define BB 16384

__device__ float g_mempre[(size_t)BB * 4096];   // 256 MB
__device__ float g_ww[BB * 64];                 //   4 MB

__device__ __forceinline__ float sigmoidf_(float x) { return 1.0f / (1.0f + __expf(-x)); }

__device__ __forceinline__ uint32_t smem_u32(const void* p) {
    uint32_t a;
    asm("{ .reg .u64 t; cvta.to.shared.u64 t, %1; cvt.u32.u64 %0, t; }" : "=r"(a) : "l"(p));
    return a;
}
__device__ __forceinline__ void ldsm4(uint32_t* d, uint32_t addr) {
    asm volatile("ldmatrix.sync.aligned.m8n8.x4.shared.b16 {%0,%1,%2,%3}, [%4];"
        : "=r"(d[0]), "=r"(d[1]), "=r"(d[2]), "=r"(d[3]) : "r"(addr));
}
__device__ __forceinline__ void mma8(float* c, const uint32_t* a, uint32_t b0, uint32_t b1) {
    asm volatile("mma.sync.aligned.m16n8k8.row.col.f32.tf32.tf32.f32 "
        "{%0,%1,%2,%3}, {%4,%5,%6,%7}, {%8,%9}, {%0,%1,%2,%3};"
        : "+f"(c[0]), "+f"(c[1]), "+f"(c[2]), "+f"(c[3])
        : "r"(a[0]), "r"(a[1]), "r"(a[2]), "r"(a[3]), "r"(b0), "r"(b1));
}
__device__ __forceinline__ void cp16(uint32_t dst, const void* src) {
    asm volatile("cp.async.cg.shared.global [%0], [%1], 16;" :: "r"(dst), "l"(src));
}
__device__ __forceinline__ void cp4(uint32_t dst, const void* src) {
    asm volatile("cp.async.ca.shared.global [%0], [%1], 4;" :: "r"(dst), "l"(src));
}
__device__ __forceinline__ void cp_commit() {
    asm volatile("cp.async.commit_group;" ::: "memory");
}
template <int N>
__device__ __forceinline__ void cp_wait() {
    asm volatile("cp.async.wait_group %0;" :: "n"(N) : "memory");
}
// B-operand x4: one k8 step, two n8 tiles (pair p)
__device__ __forceinline__ uint32_t boff4(int NB, int wn, int NW, int p, int lane) {
    return (uint32_t)(((((lane >> 3) & 1) * NB) + wn * NW + p * 16 +
                      (lane & 7) + ((lane >> 4) << 3)) * 16);
}
// swizzled mv/mempre chunk address (128-row tiles)
__device__ __forceinline__ uint32_t r1a(int kb, int row) {
    return (uint32_t)((kb * 128 + (row ^ (kb & 7))) * 16);
}

// ---- SMEM map (bytes), total 221184 ----
// [0,65536)        c0 chunks (128r x 128k A-chunk); later e1 @0 (32K), z1/add @32768
// P1:  3 x 32768 pipeline stages @65536..163840; c0-epi stage 128x132 @65536
// P3:  MV 2x16K @65536/81920 | WM 2x16K @98304/114688 | WS 2x24K @131072/155648
// P4a: siga 96K @65536 | EZ B 32K @163840
// P4b: zt chunk 16K @163840 | Wza half 8K @180224
// P5:  ww 32K @188416
#define MV_OFF0 65536
#define MV_OFF1 81920
#define WM_OFF0 98304
#define WM_OFF1 114688
#define WS_OFF0 131072
#define WS_OFF1 155648
#define SMEM_TOTAL 221184

__global__ void __launch_bounds__(512, 1) fused_k(
    const float* __restrict__ qa,  const float* __restrict__ mv,
    const float* __restrict__ We,  const float* __restrict__ be,
    const float* __restrict__ Wemv, const float* __restrict__ bemv,
    const float* __restrict__ Wza, const float* __restrict__ bza,
    const float* __restrict__ Wamv, const float* __restrict__ bamv,
    const float* __restrict__ Wc0, const float* __restrict__ bc0,
    const float* __restrict__ Wm1, const float* __restrict__ bm1,
    const float* __restrict__ Wz,  const float* __restrict__ bz,
    const float* __restrict__ Wzmv, const float* __restrict__ bzmv,
    float* __restrict__ outp)
{
    extern __shared__ char smem[];
    const int tid  = threadIdx.x;
    const int lane = tid & 31;
    const int wid  = tid >> 5;
    const int wm   = wid & 3;
    const int wn   = wid >> 2;
    const int m0   = blockIdx.x * 128;

    uint32_t sb  = smem_u32(smem);
    uint32_t c0b = sb;

    const uint32_t aoff0 = (uint32_t)((((lane >> 4) * 128) + wm * 32 + (lane & 15)) * 16);
    const uint32_t aoff1 = aoff0 + 256;
    const uint32_t gbo   = boff4(64, wn, 16, 0, lane);           // NB=64 (P4a/P4b)
    const uint32_t boffG = (uint32_t)(((lane >> 3) * 32 + wn * 8 + (lane & 7)) * 16); // NB=32 gate B
    const int frow0 = wm * 32 + (lane >> 2);
    const int fc2   = 2 * (lane & 3);

    // ============ P1: c0 = qa * sigmoid(mv @ Wc0 + bc0), 3-stage pipeline ============
    {
        float cacc[2][4][4];
#pragma unroll
        for (int mt = 0; mt < 2; mt++)
#pragma unroll
            for (int nt = 0; nt < 4; nt++)
#pragma unroll
                for (int j = 0; j < 4; j++) cacc[mt][nt][j] = 0.f;

        auto issue1 = [&](int c) {
            uint32_t ab = sb + 65536 + (c % 3) * 32768, bb2 = ab + 16384;
            int kt = c * 32;
#pragma unroll
            for (int i = 0; i < 2; i++) {
                int v = tid + i * 512;
                int kq = v & 7, r = v >> 3;
                cp16(ab + (kq * 128 + r) * 16, &mv[(size_t)(m0 + r) * 4096 + kt + kq * 4]);
            }
#pragma unroll
            for (int i = 0; i < 8; i++) {
                int v = tid + i * 512;
                int kl = v >> 7, n = v & 127;
                cp4(bb2 + ((kl >> 2) * 128 + n) * 16 + (kl & 3) * 4,
                    &Wc0[(size_t)(kt + kl) * 128 + n]);
            }
            cp_commit();
        };
        issue1(0); issue1(1);
#pragma unroll 1
        for (int c = 0; c < 128; c++) {
            if (c == 127) cp_wait<0>(); else cp_wait<1>();
            __syncthreads();
            if (c + 2 < 128) issue1(c + 2);
            uint32_t ab = sb + 65536 + (c % 3) * 32768, bb2 = ab + 16384;
#pragma unroll
            for (int s = 0; s < 4; s++) {
                uint32_t a0[4], a1[4];
                ldsm4(a0, ab + aoff0 + s * 4096);
                ldsm4(a1, ab + aoff1 + s * 4096);
#pragma unroll
                for (int p = 0; p < 2; p++) {
                    uint32_t b[4];
                    ldsm4(b, bb2 + boff4(128, wn, 32, p, lane) + s * 4096);
                    mma8(cacc[0][2 * p],     a0, b[0], b[1]);
                    mma8(cacc[0][2 * p + 1], a0, b[2], b[3]);
                    mma8(cacc[1][2 * p],     a1, b[0], b[1]);
                    mma8(cacc[1][2 * p + 1], a1, b[2], b[3]);
                }
            }
        }
        __syncthreads();
        float* stg = (float*)(smem + 65536);
#pragma unroll
        for (int mt = 0; mt < 2; mt++)
#pragma unroll
            for (int nt = 0; nt < 4; nt++) {
                int row = frow0 + mt * 16;
                int col = wn * 32 + nt * 8 + fc2;
                *(float2*)&stg[row * 132 + col]       = make_float2(cacc[mt][nt][0], cacc[mt][nt][1]);
                *(float2*)&stg[(row + 8) * 132 + col] = make_float2(cacc[mt][nt][2], cacc[mt][nt][3]);
            }
        __syncthreads();
#pragma unroll
        for (int i = 0; i < 32; i++) {
            int v = tid + i * 512;
            int row = v >> 7, k = v & 127;
            float c0v = __ldg(&qa[(size_t)(m0 + row) * 128 + k]) *
                        sigmoidf_(stg[row * 132 + k] + __ldg(&bc0[k]));
            *(float*)(smem + ((k >> 2) * 128 + row) * 16 + (k & 3) * 4) = c0v;
        }
        __syncthreads();
    }

    // ============ P3: pipelined 32-col blocks; burst = SIG(o) + gate(o+1) ============
    float sacc[2][6][4];
#pragma unroll
    for (int mt = 0; mt < 2; mt++)
#pragma unroll
        for (int nt = 0; nt < 6; nt++)
#pragma unroll
            for (int j = 0; j < 4; j++) sacc[mt][nt][j] = 0.f;
    float gacc[2][4];
#pragma unroll
    for (int mt = 0; mt < 2; mt++)
#pragma unroll
        for (int j = 0; j < 4; j++) gacc[mt][j] = 0.f;
    {
        auto load_mv = [&](int o) {                  // mv(o) -> MV[o&1]
            int kt = o * 32;
            uint32_t dst = sb + ((o & 1) ? MV_OFF1 : MV_OFF0);
#pragma unroll
            for (int i = 0; i < 2; i++) {
                int v = tid + i * 512;
                int kb = v & 7, r = v >> 3;
                cp16(dst + r1a(kb, r), &mv[(size_t)(m0 + r) * 4096 + kt + kb * 4]);
            }
        };
        auto load_wm = [&](int o) {                  // Wm1 slice o -> WM[o&1]
            int kt = o * 32;
            uint32_t dst = sb + ((o & 1) ? WM_OFF1 : WM_OFF0);
#pragma unroll
            for (int i = 0; i < 8; i++) {
                int v = tid + i * 512;
                int kl = v >> 5, n = v & 31;
                cp4(dst + ((kl >> 2) * 32 + n) * 16 + (kl & 3) * 4,
                    &Wm1[(size_t)kl * 4096 + kt + n]);
            }
        };
        auto load_ws = [&](int o) {                  // Wsig chunk o -> WS[o&1]
            int kt = o * 32;
            uint32_t dst = sb + ((o & 1) ? WS_OFF1 : WS_OFF0);
#pragma unroll
            for (int i = 0; i < 12; i++) {
                int v = tid + i * 512;
                int kl = v / 192, n = v - kl * 192;
                const float* W = (n < 64) ? Wemv : (n < 128) ? Wzmv : Wamv;
                cp4(dst + ((kl >> 2) * 192 + n) * 16 + (kl & 3) * 4,
                    &W[(size_t)(kt + kl) * 64 + (n & 63)]);
            }
        };
        auto gate_mma = [&](uint32_t wmb) {          // A = c0 (K=128), B NB=32
#pragma unroll
            for (int s = 0; s < 8; s++) {
                uint32_t ae0[4], ae1[4], ao0[4], ao1[4], b[4];
                ldsm4(ae0, c0b + aoff0 + (2 * s) * 4096);
                ldsm4(ae1, c0b + aoff1 + (2 * s) * 4096);
                ldsm4(ao0, c0b + aoff0 + (2 * s + 1) * 4096);
                ldsm4(ao1, c0b + aoff1 + (2 * s + 1) * 4096);
                ldsm4(b, wmb + boffG + s * 2048);
                mma8(gacc[0], ae0, b[0], b[1]);
                mma8(gacc[1], ae1, b[0], b[1]);
                mma8(gacc[0], ao0, b[2], b[3]);
                mma8(gacc[1], ao1, b[2], b[3]);
            }
        };

        // prologue: A0 = {mv(0), Wm1(0)}, B0 = {mv(1), Wm1(1), Wsig(0)}; gate(0)
        load_mv(0); load_wm(0); cp_commit();
        load_mv(1); load_wm(1); load_ws(0); cp_commit();
        cp_wait<1>();
        __syncthreads();
        gate_mma(sb + WM_OFF0);

#pragma unroll 1
        for (int o = 0; o < 128; o++) {
            cp_wait<0>();
            __syncthreads();                         // G(o-1) visible; burst(o-1) done
            if (o < 127) {                           // G(o): loads for iter o+1
                load_mv(o + 1);
                if (o + 2 < 128) load_wm(o + 2);
                load_ws(o + 1);
                cp_commit();
            }

            // epilogue(o): mempre = mv * sigmoid(gacc + bm1), in place + STG
            const int kt = o * 32;
            const int mvoff = (o & 1) ? MV_OFF1 : MV_OFF0;
            {
                int colb = wn * 8 + fc2;
                float b0v = __ldg(&bm1[kt + colb]);
                float b1v = __ldg(&bm1[kt + colb + 1]);
                int kb = colb >> 2, w0 = colb & 3;
#pragma unroll
                for (int mt = 0; mt < 2; mt++)
#pragma unroll
                    for (int half = 0; half < 2; half++) {
                        int row = frow0 + mt * 16 + half * 8;
                        uint32_t off = mvoff + r1a(kb, row) + w0 * 4;
                        float p0 = *(float*)(smem + off) *
                                   sigmoidf_(gacc[mt][half * 2 + 0] + b0v);
                        float p1 = *(float*)(smem + off + 4) *
                                   sigmoidf_(gacc[mt][half * 2 + 1] + b1v);
                        *(float*)(smem + off)     = p0;
                        *(float*)(smem + off + 4) = p1;
                        *(float2*)&g_mempre[(size_t)(m0 + row) * 4096 + kt + colb] =
                            make_float2(p0, p1);
                    }
            }
#pragma unroll
            for (int mt = 0; mt < 2; mt++)
#pragma unroll
                for (int j = 0; j < 4; j++) gacc[mt][j] = 0.f;
            __syncthreads();                         // mempre(o) visible

            // burst: SIG(o) then gate(o+1), no barrier between
            {
                uint32_t mvb = sb + mvoff;
                uint32_t wsb = sb + ((o & 1) ? WS_OFF1 : WS_OFF0);
                const int rowb = wm * 32 + (lane & 15);
#pragma unroll
                for (int s = 0; s < 4; s++) {
                    int kb0 = 2 * s + (lane >> 4);
                    uint32_t a0[4], a1[4];
                    ldsm4(a0, mvb + (uint32_t)((kb0 * 128 + (rowb ^ (kb0 & 7))) * 16));
                    ldsm4(a1, mvb + (uint32_t)((kb0 * 128 + ((rowb + 16) ^ (kb0 & 7))) * 16));
#pragma unroll
                    for (int p = 0; p < 3; p++) {
                        uint32_t b[4];
                        ldsm4(b, wsb + boff4(192, wn, 48, p, lane) + s * 6144);
                        mma8(sacc[0][2 * p],     a0, b[0], b[1]);
                        mma8(sacc[0][2 * p + 1], a0, b[2], b[3]);
                        mma8(sacc[1][2 * p],     a1, b[0], b[1]);
                        mma8(sacc[1][2 * p + 1], a1, b[2], b[3]);
                    }
                }
                if (o < 127)
                    gate_mma(sb + (((o + 1) & 1) ? WM_OFF1 : WM_OFF0));
            }
        }
    }

    // ============ P4a: sacc dump -> siga; EZ = c0 @ [We|Wz] ============
    __syncthreads();
    {
        auto issue_ez = [&](const float* W) {
#pragma unroll
            for (int i = 0; i < 16; i++) {
                int v = tid + i * 512;
                int kl = v >> 6, n = v & 63;
                cp4(sb + 163840 + ((kl >> 2) * 64 + n) * 16 + (kl & 3) * 4,
                    &W[(size_t)kl * 64 + n]);
            }
            cp_commit();
        };
        issue_ez(We);
        float* siga = (float*)(smem + 65536);
#pragma unroll
        for (int mt = 0; mt < 2; mt++)
#pragma unroll
            for (int nt = 0; nt < 6; nt++)
#pragma unroll
                for (int idx = 0; idx < 4; idx++) {
                    int row = frow0 + mt * 16 + (idx >> 1) * 8;
                    int col = wn * 48 + nt * 8 + fc2 + (idx & 1);
                    float bv = (col < 64) ? __ldg(&bemv[col])
                             : (col < 128) ? __ldg(&bzmv[col - 64])
                                           : __ldg(&bamv[col - 128]);
                    siga[row * 192 + col] = sacc[mt][nt][idx] + bv;
                }
        cp_wait<0>(); __syncthreads();

        float eacc[2][2][4], zacc[2][2][4];
#pragma unroll
        for (int mt = 0; mt < 2; mt++)
#pragma unroll
            for (int nt = 0; nt < 2; nt++)
#pragma unroll
                for (int j = 0; j < 4; j++) { eacc[mt][nt][j] = 0.f; zacc[mt][nt][j] = 0.f; }
#pragma unroll
        for (int s = 0; s < 16; s++) {
            uint32_t a0[4], a1[4], b[4];
            ldsm4(a0, c0b + aoff0 + s * 4096);
            ldsm4(a1, c0b + aoff1 + s * 4096);
            ldsm4(b, sb + 163840 + gbo + s * 2048);
            mma8(eacc[0][0], a0, b[0], b[1]);
            mma8(eacc[0][1], a0, b[2], b[3]);
            mma8(eacc[1][0], a1, b[0], b[1]);
            mma8(eacc[1][1], a1, b[2], b[3]);
        }
        __syncthreads();
        issue_ez(Wz);
        cp_wait<0>(); __syncthreads();
#pragma unroll
        for (int s = 0; s < 16; s++) {
            uint32_t a0[4], a1[4], b[4];
            ldsm4(a0, c0b + aoff0 + s * 4096);
            ldsm4(a1, c0b + aoff1 + s * 4096);
            ldsm4(b, sb + 163840 + gbo + s * 2048);
            mma8(zacc[0][0], a0, b[0], b[1]);
            mma8(zacc[0][1], a0, b[2], b[3]);
            mma8(zacc[1][0], a1, b[0], b[1]);
            mma8(zacc[1][1], a1, b[2], b[3]);
        }
        __syncthreads();  // c0 reads complete before overwrite
        float* e1a = (float*)smem;
        float* z1a = (float*)(smem + 32768);
#pragma unroll
        for (int mt = 0; mt < 2; mt++)
#pragma unroll
            for (int nt = 0; nt < 2; nt++)
#pragma unroll
                for (int idx = 0; idx < 4; idx++) {
                    int row = frow0 + mt * 16 + (idx >> 1) * 8;
                    int col = wn * 16 + nt * 8 + fc2 + (idx & 1);
                    e1a[row * 64 + col] = sigmoidf_(eacc[mt][nt][idx] + __ldg(&be[col]));
                    z1a[row * 64 + col] = zacc[mt][nt][idx] + __ldg(&bz[col]);
                }
        __syncthreads();
    }

    // ============ P4b: zt, erase, add ============
    {
        float* e1a  = (float*)smem;
        float* z1a  = (float*)(smem + 32768);
        float* siga = (float*)(smem + 65536);

        float zaacc[2][2][4];
#pragma unroll
        for (int mt = 0; mt < 2; mt++)
#pragma unroll
            for (int nt = 0; nt < 2; nt++)
#pragma unroll
                for (int j = 0; j < 4; j++) zaacc[mt][nt][j] = 0.f;

#pragma unroll 1
        for (int h = 0; h < 2; h++) {
#pragma unroll
            for (int i = 0; i < 4; i++) {
                int v = tid + i * 512;
                int kl = v >> 6, n = v & 63;
                cp4(sb + 180224 + ((kl >> 2) * 64 + n) * 16 + (kl & 3) * 4,
                    &Wza[(size_t)(h * 32 + kl) * 64 + n]);
            }
            cp_commit();
#pragma unroll
            for (int i = 0; i < 8; i++) {
                int v = tid + i * 512;
                int row = v >> 5, jl = v & 31;
                int j = h * 32 + jl;
                float ztv = sigmoidf_(z1a[row * 64 + j] + siga[row * 192 + 64 + j]);
                *(float*)(smem + 163840 + ((jl >> 2) * 128 + row) * 16 + (jl & 3) * 4) = ztv;
                e1a[row * 64 + j] = sigmoidf_(e1a[row * 64 + j] + sigmoidf_(siga[row * 192 + j]));
            }
            cp_wait<0>(); __syncthreads();
#pragma unroll
            for (int s = 0; s < 4; s++) {
                uint32_t a0[4], a1[4], b[4];
                ldsm4(a0, sb + 163840 + aoff0 + s * 4096);
                ldsm4(a1, sb + 163840 + aoff1 + s * 4096);
                ldsm4(b, sb + 180224 + gbo + s * 2048);
                mma8(zaacc[0][0], a0, b[0], b[1]);
                mma8(zaacc[0][1], a0, b[2], b[3]);
                mma8(zaacc[1][0], a1, b[0], b[1]);
                mma8(zaacc[1][1], a1, b[2], b[3]);
            }
            __syncthreads();
        }
#pragma unroll
        for (int mt = 0; mt < 2; mt++)
#pragma unroll
            for (int nt = 0; nt < 2; nt++)
#pragma unroll
                for (int idx = 0; idx < 4; idx++) {
                    int row = frow0 + mt * 16 + (idx >> 1) * 8;
                    int col = wn * 16 + nt * 8 + fc2 + (idx & 1);
                    z1a[row * 64 + col] =
                        tanhf(tanhf(zaacc[mt][nt][idx] + __ldg(&bza[col])) +
                              tanhf(siga[row * 192 + 128 + col]));
                }
        __syncthreads();
#pragma unroll
        for (int i = 0; i < 4; i++) {
            int v = tid + i * 512;
            *(float4*)(smem + 188416 + v * 16) = *(const float4*)&g_ww[(size_t)m0 * 64 + v * 4];
        }
        __syncthreads();
    }

    // ============ P5: out = mempre*(1 - w*erase) + w*add ============
    {
        const float* er = (const float*)smem;
        const float* ad = (const float*)(smem + 32768);
        const float* sw = (const float*)(smem + 188416);
#pragma unroll 4
        for (int it = 0; it < 256; it++) {
            int v = tid + it * 512;
            int row = v >> 10, q = v & 1023;
            float4 mp = *(const float4*)&g_mempre[(size_t)(m0 + row) * 4096 + q * 4];
            float w = sw[row * 64 + (q >> 4)];
            float4 e4 = *(const float4*)&er[row * 64 + (q & 15) * 4];
            float4 a4 = *(const float4*)&ad[row * 64 + (q & 15) * 4];
            float4 r;
            r.x = mp.x * (1.f - w * e4.x) + w * a4.x;
            r.y = mp.y * (1.f - w * e4.y) + w * a4.y;
            r.z = mp.z * (1.f - w * e4.z) + w * a4.z;
            r.w = mp.w * (1.f - w * e4.w) + w * a4.w;
            *(float4*)&outp[(size_t)(m0 + row) * 4096 + q * 4] = r;
        }
    }
}

// ---------------- write_weight: softmax(control_key @ memory_key^T) ----------------
__global__ void __launch_bounds__(256) ww_k(const float* __restrict__ ck,
                                            const float* __restrict__ mk)
{
    int g = threadIdx.x >> 6;
    int t = threadIdx.x & 63;
    int b = blockIdx.x * 4 + g;
    __shared__ float sck[4][64];
    __shared__ float pmax[4][2];
    __shared__ float psum[4][2];

    sck[g][t] = ck[b * 64 + t];
    __syncthreads();
    float dot = 0.f;
#pragma unroll 8
    for (int k = 0; k < 64; k++) dot = fmaf(sck[g][k], mk[t * 64 + k], dot);

    float mx = dot;
#pragma unroll
    for (int o = 16; o > 0; o >>= 1) mx = fmaxf(mx, __shfl_xor_sync(0xffffffffu, mx, o));
    int wl = t >> 5;
    if ((t & 31) == 0) pmax[g][wl] = mx;
    __syncthreads();
    mx = fmaxf(pmax[g][0], pmax[g][1]);

    float e = __expf(dot - mx);
    float s = e;
#pragma unroll
    for (int o = 16; o > 0; o >>= 1) s += __shfl_xor_sync(0xffffffffu, s, o);
    if ((t & 31) == 0) psum[g][wl] = s;
    __syncthreads();
    s = psum[g][0] + psum[g][1];

    g_ww[b * 64 + t] = e / s;
}

// ====================== launch ======================
extern "C" void kernel_launch(void* const* d_in, const int* in_sizes, int n_in,
                              void* d_out, int out_size)
{
    const float* control_key  = (const float*)d_in[0];
    const float* control_qa   = (const float*)d_in[1];
    const float* memory_key   = (const float*)d_in[2];
    const float* memory_value = (const float*)d_in[3];
    const float* We   = (const float*)d_in[4];
    const float* be   = (const float*)d_in[5];
    const float* Wemv = (const float*)d_in[6];
    const float* bemv = (const float*)d_in[7];
    const float* Wza  = (const float*)d_in[8];
    const float* bza  = (const float*)d_in[9];
    const float* Wamv = (const float*)d_in[10];
    const float* bamv = (const float*)d_in[11];
    const float* Wc0  = (const float*)d_in[12];
    const float* bc0  = (const float*)d_in[13];
    const float* Wm1  = (const float*)d_in[14];
    const float* bm1  = (const float*)d_in[15];
    const float* Wz   = (const float*)d_in[16];
    const float* bz   = (const float*)d_in[17];
    const float* Wzmv = (const float*)d_in[18];
    const float* bzmv = (const float*)d_in[19];
    float* out = (float*)d_out;

    cudaFuncSetAttribute(fused_k, cudaFuncAttributeMaxDynamicSharedMemorySize, SMEM_TOTAL);

    ww_k<<<BB / 4, 256>>>(control_key, memory_key);

    fused_k<<<BB / 128, 512, SMEM_TOTAL>>>(
        control_qa, memory_value,
        We, be, Wemv, bemv, Wza, bza, Wamv, bamv,
        Wc0, bc0, Wm1, bm1, Wz, bz, Wzmv, bzmv,
        out);
}